// round 2
// baseline (speedup 1.0000x reference)
#include <cuda_runtime.h>
#include <math.h>

#define TM 128
#define TN 128
#define DD 64
#define NTHREADS 256

// scratch (no allocations allowed)
__device__ float g_enorm[2048];
__device__ float g_ET[2048 * DD];
__device__ int   g_hist[2048];
__device__ float g_partial[8192];

static __device__ __forceinline__ unsigned long long pack2(float v) {
    unsigned long long r;
    asm("mov.b64 %0, {%1, %1};" : "=l"(r) : "f"(v));
    return r;
}
static __device__ __forceinline__ unsigned long long fma2(unsigned long long a,
                                                          unsigned long long b,
                                                          unsigned long long c) {
    unsigned long long d;
    asm("fma.rn.f32x2 %0, %1, %2, %3;" : "=l"(d) : "l"(a), "l"(b), "l"(c));
    return d;
}
static __device__ __forceinline__ void unpack2(unsigned long long v, float& lo, float& hi) {
    asm("mov.b64 {%0, %1}, %2;" : "=f"(lo), "=f"(hi) : "l"(v));
}

// Setup: codebook column norms (sequential fp32 mul+add, matching jnp.sum order),
// transposed codebook (for coalesced gather), zero histogram.
__global__ void vq_setup(const float* __restrict__ E, int K) {
    int k = blockIdx.x * blockDim.x + threadIdx.x;
    if (k < K) {
        float s = 0.f;
#pragma unroll
        for (int d = 0; d < DD; d++) {
            float v = E[d * K + k];
            s = __fadd_rn(s, __fmul_rn(v, v));   // sequential, no fma
            g_ET[k * DD + d] = v;
        }
        g_enorm[k] = s;
        g_hist[k] = 0;
    }
}

__global__ __launch_bounds__(NTHREADS)
void vq_main(const float* __restrict__ X, const float* __restrict__ E,
             float* __restrict__ out, int rows, int K)
{
    extern __shared__ float smem[];
    float* Xs  = smem;                         // TM*DD  (row-major [row][d])
    float* Es  = Xs + TM * DD;                 // DD*TN  ([d][col])
    float* Ee  = Es + DD * TN;                 // TN     (||e||^2 tile)
    float* red = Ee + TN;                      // NTHREADS
    float* Xxs = red + NTHREADS;               // TM     (||x||^2 per row)
    int*  bIdx = (int*)(Xxs + TM);             // TM

    int tid = threadIdx.x;
    int tx = tid & 15, ty = tid >> 4;
    int r0 = blockIdx.x * TM;

    // Load X tile (coalesced float4, clamped for safety)
    {
        const float4* Xg4 = (const float4*)X;
        float4* Xs4 = (float4*)Xs;
        int maxq = rows * (DD / 4) - 1;
#pragma unroll
        for (int i = 0; i < (TM * DD / 4) / NTHREADS; i++) {
            int idx = tid + i * NTHREADS;
            int g = r0 * (DD / 4) + idx;
            Xs4[idx] = Xg4[g <= maxq ? g : maxq];
        }
    }
    __syncthreads();

    // ||x||^2 per row: sequential fp32 (no fma) to match reference reduction order
    if (tid < TM) {
        float s = 0.f;
#pragma unroll
        for (int d = 0; d < DD; d++) {
            float v = Xs[tid * DD + d];
            s = __fadd_rn(s, __fmul_rn(v, v));
        }
        Xxs[tid] = s;
    }
    __syncthreads();

    float xx[8];
#pragma unroll
    for (int i = 0; i < 8; i++) xx[i] = Xxs[ty * 8 + i];

    float bestV[8];
    int   bestI[8];
#pragma unroll
    for (int i = 0; i < 8; i++) { bestV[i] = 1e30f; bestI[i] = 0; }

    const int kq = K >> 2;
    for (int kt = 0; kt < K; kt += TN) {
        __syncthreads();
        {
            const float4* Eg4 = (const float4*)E;
            float4* Es4 = (float4*)Es;
#pragma unroll
            for (int i = 0; i < (DD * TN / 4) / NTHREADS; i++) {
                int idx = tid + i * NTHREADS;
                int d = idx >> 5, c4 = idx & 31;
                Es4[idx] = Eg4[d * kq + (kt >> 2) + c4];
            }
            if (tid < TN) Ee[tid] = g_enorm[kt + tid];
        }
        __syncthreads();

        // 8 rows x 8 cols per thread, packed f32x2 accumulators (pairs of cols).
        // Each lane is a strict sequential fma chain over d=0..63 — bitwise
        // identical to SGEMM / Eigen per-output accumulation.
        unsigned long long acc[8][4];
#pragma unroll
        for (int i = 0; i < 8; i++)
#pragma unroll
            for (int j = 0; j < 4; j++) acc[i][j] = 0ULL;

        const float4* Xs4 = (const float4*)Xs;
#pragma unroll 4
        for (int d4 = 0; d4 < DD / 4; d4++) {
            float4 a4[8];
#pragma unroll
            for (int i = 0; i < 8; i++) a4[i] = Xs4[(ty * 8 + i) * (DD / 4) + d4];
#pragma unroll
            for (int s = 0; s < 4; s++) {
                const ulonglong2* bp = (const ulonglong2*)(Es + (d4 * 4 + s) * TN + tx * 8);
                ulonglong2 bA = bp[0];
                ulonglong2 bB = bp[1];
#pragma unroll
                for (int i = 0; i < 8; i++) {
                    float av = (s == 0) ? a4[i].x : ((s == 1) ? a4[i].y : ((s == 2) ? a4[i].z : a4[i].w));
                    unsigned long long aa = pack2(av);
                    acc[i][0] = fma2(aa, bA.x, acc[i][0]);
                    acc[i][1] = fma2(aa, bA.y, acc[i][1]);
                    acc[i][2] = fma2(aa, bB.x, acc[i][2]);
                    acc[i][3] = fma2(aa, bB.y, acc[i][3]);
                }
            }
        }

        // Emulated reference rounding chain:
        // dist = fl( fl(xx - fl(2*s)) + ee ), running min with first-index tie-break.
#pragma unroll
        for (int i = 0; i < 8; i++) {
#pragma unroll
            for (int j = 0; j < 4; j++) {
                float lo, hi;
                unpack2(acc[i][j], lo, hi);
                int cl = tx * 8 + j * 2;
                float d0 = __fadd_rn(__fsub_rn(xx[i], __fmul_rn(2.0f, lo)), Ee[cl]);
                float d1 = __fadd_rn(__fsub_rn(xx[i], __fmul_rn(2.0f, hi)), Ee[cl + 1]);
                int c0 = kt + cl;
                if (d0 < bestV[i]) { bestV[i] = d0; bestI[i] = c0; }
                if (d1 < bestV[i]) { bestV[i] = d1; bestI[i] = c0 + 1; }
            }
        }
    }

    // reduce across the 16 col-threads per row (min dist, tie -> smaller index)
#pragma unroll
    for (int off = 8; off > 0; off >>= 1) {
#pragma unroll
        for (int i = 0; i < 8; i++) {
            float ov = __shfl_xor_sync(0xffffffffu, bestV[i], off);
            int   oi = __shfl_xor_sync(0xffffffffu, bestI[i], off);
            if (ov < bestV[i] || (ov == bestV[i] && oi < bestI[i])) { bestV[i] = ov; bestI[i] = oi; }
        }
    }
    if (tx == 0) {
#pragma unroll
        for (int i = 0; i < 8; i++) bIdx[ty * 8 + i] = bestI[i];
    }
    __syncthreads();

    // histogram (int atomics — deterministic)
    if (tid < TM && (r0 + tid) < rows) atomicAdd(&g_hist[bIdx[tid]], 1);

    // gather codebook rows (pre-transposed, coalesced), emulate STE rounding,
    // write q, accumulate SSE on raw (q - x)
    float sse = 0.f;
#pragma unroll
    for (int i = 0; i < (TM * DD) / NTHREADS; i++) {
        int e = tid + i * NTHREADS;
        int row = e >> 6, d = e & 63;
        if (r0 + row < rows) {
            float qv = g_ET[bIdx[row] * DD + d];
            float xv = Xs[row * DD + d];
            float df = __fsub_rn(qv, xv);
            out[(size_t)(r0 + row) * DD + d] = __fadd_rn(xv, df);  // q = x + (q - x), ref rounding
            sse += df * df;
        }
    }
    red[tid] = sse;
    __syncthreads();
    for (int off = NTHREADS / 2; off > 0; off >>= 1) {
        if (tid < off) red[tid] += red[tid + off];
        __syncthreads();
    }
    if (tid == 0) g_partial[blockIdx.x] = red[0];
}

__global__ void vq_finalize(float* __restrict__ out, int nblocks, int rows, int K, long long outsz) {
    __shared__ float sh[1024];
    int tid = threadIdx.x;

    float s = 0.f;
    for (int i = tid; i < nblocks; i += blockDim.x) s += g_partial[i];
    sh[tid] = s;
    __syncthreads();
    for (int off = 512; off > 0; off >>= 1) {
        if (tid < off) sh[tid] += sh[tid + off];
        __syncthreads();
    }
    float sse = sh[0];
    __syncthreads();

    float invN = 1.0f / (float)rows;
    float ent = 0.f;
    for (int k = tid; k < K; k += blockDim.x) {
        float p = (float)g_hist[k] * invN;
        ent += p * logf(p + 1e-10f);
    }
    sh[tid] = ent;
    __syncthreads();
    for (int off = 512; off > 0; off >>= 1) {
        if (tid < off) sh[tid] += sh[tid + off];
        __syncthreads();
    }

    if (tid == 0) {
        long long nd = (long long)rows * DD;
        // loss = 1.0 * l_commitment + l_codebook, both == mean((q-x)^2) forward
        if (outsz > nd)     out[nd]     = 2.f * sse / (float)nd;
        if (outsz > nd + 1) out[nd + 1] = expf(-sh[0]);
    }
}

extern "C" void kernel_launch(void* const* d_in, const int* in_sizes, int n_in,
                              void* d_out, int out_size) {
    const float* X = (const float*)d_in[0];
    const float* E = (const float*)d_in[1];
    float* out = (float*)d_out;

    int nd = in_sizes[0];
    int rows = nd / DD;              // 131072
    int K = in_sizes[1] / DD;        // 1024

    int grid = (rows + TM - 1) / TM; // 1024

    size_t smem = (size_t)(TM * DD + DD * TN + TN + NTHREADS + TM) * sizeof(float) + TM * sizeof(int);
    cudaFuncSetAttribute(vq_main, cudaFuncAttributeMaxDynamicSharedMemorySize, (int)smem);

    vq_setup<<<(K + 255) / 256, 256>>>(E, K);
    vq_main<<<grid, NTHREADS, smem>>>(X, E, out, rows, K);
    vq_finalize<<<1, 1024>>>(out, grid, rows, K, (long long)out_size);
}

// round 8
// speedup vs baseline: 1.0265x; 1.0265x over previous
#include <cuda_runtime.h>
#include <cuda_bf16.h>
#include <cstdint>
#include <math.h>

#define DD 64
#define KTOT 1024
#define TM 128
#define NTHREADS 256
#define NTILE 64
#define NKT (KTOT / NTILE)
#define CAP 6
#define EPS 8e-3f

// ---------------- scratch (no allocations allowed) ----------------
__device__ float          g_enorm[KTOT];
__device__ float          g_ET[KTOT * DD];      // codebook rows, k-major, f32
__device__ __nv_bfloat16  g_Bhi[KTOT * DD];     // bf16 hi split, [code][d]
__device__ __nv_bfloat16  g_Blo[KTOT * DD];     // bf16 lo split, [code][d]
__device__ int            g_hist[KTOT];
__device__ float          g_partial[2048];

// ---------------- PTX helpers (baseline PTX only, no 'a' features) ---------
static __device__ __forceinline__ uint32_t smem_to_u32(const void* p) {
    uint32_t a;
    asm("{ .reg .u64 t; cvta.to.shared.u64 t, %1; cvt.u32.u64 %0, t; }" : "=r"(a) : "l"(p));
    return a;
}
static __device__ __forceinline__ void ldsm4(uint32_t& r0, uint32_t& r1,
    uint32_t& r2, uint32_t& r3, uint32_t addr) {
    asm volatile("ldmatrix.sync.aligned.m8n8.x4.shared.b16 {%0,%1,%2,%3}, [%4];"
        : "=r"(r0), "=r"(r1), "=r"(r2), "=r"(r3) : "r"(addr));
}
static __device__ __forceinline__ void mma_bf16(float* c, const uint32_t* a,
    uint32_t b0, uint32_t b1) {
    asm volatile(
        "mma.sync.aligned.m16n8k16.row.col.f32.bf16.bf16.f32 "
        "{%0,%1,%2,%3}, {%4,%5,%6,%7}, {%8,%9}, {%0,%1,%2,%3};"
        : "+f"(c[0]), "+f"(c[1]), "+f"(c[2]), "+f"(c[3])
        : "r"(a[0]), "r"(a[1]), "r"(a[2]), "r"(a[3]), "r"(b0), "r"(b1));
}
static __device__ __forceinline__ uint32_t swz128(uint32_t off) {
    return off ^ ((off >> 3) & 0x70u);
}

// ---------------- SMEM layout (bytes) ----------------
#define SM_XS    0          // 128*64 f32 = 32768
#define SM_AHI   32768      // 128*64 bf16 = 16384 (SW128 swizzled)
#define SM_ALO   49152      // 16384
#define SM_BHI   65536      // 64*64 bf16 = 8192
#define SM_BLO   73728      // 8192
#define SM_EE    81920      // 64 f32
#define SM_XX    82176      // 128 f32
#define SM_RED   82688      // 256 f32
#define SM_BIDX  83712      // 128 int
#define SM_TOTAL 84224

// ---------------- setup: norms (ref order), f32 rows, bf16 hi/lo split ------
__global__ void vq_setup(const float* __restrict__ E, int K) {
    int k = blockIdx.x * blockDim.x + threadIdx.x;
    if (k < K) {
        float s = 0.f;
#pragma unroll
        for (int d = 0; d < DD; d++) {
            float v = E[d * K + k];
            s = __fadd_rn(s, __fmul_rn(v, v));   // sequential, no fma (ref order)
            g_ET[k * DD + d] = v;
            __nv_bfloat16 h = __float2bfloat16(v);
            float hf = __bfloat162float(h);
            g_Bhi[k * DD + d] = h;
            g_Blo[k * DD + d] = __float2bfloat16(v - hf);
        }
        g_enorm[k] = s;
        g_hist[k] = 0;
    }
}

// exact reference-rounding distance (same chain that passed R2)
static __device__ __forceinline__ float exact_dist(const float* __restrict__ xr,
                                                   int k, float xxv) {
    float s = 0.f;
    const float4* ep = (const float4*)(g_ET + k * DD);
#pragma unroll
    for (int d4 = 0; d4 < DD / 4; d4++) {
        float4 e = ep[d4];
        float4 x = ((const float4*)xr)[d4];
        s = __fmaf_rn(x.x, e.x, s);
        s = __fmaf_rn(x.y, e.y, s);
        s = __fmaf_rn(x.z, e.z, s);
        s = __fmaf_rn(x.w, e.w, s);
    }
    return __fadd_rn(__fsub_rn(xxv, __fmul_rn(2.0f, s)), g_enorm[k]);
}

static __device__ __forceinline__ void cand_add(float dist, int code,
    float* cd, int* ck, int& cnt, bool& ovf, float& runm) {
    if (dist < runm + EPS) {
        if (cnt == CAP) {   // prune against current runmin
            int nc = 0;
            for (int u = 0; u < CAP; u++) {
                if (cd[u] < runm + EPS) { cd[nc] = cd[u]; ck[nc] = ck[u]; nc++; }
            }
            cnt = nc;
        }
        if (cnt < CAP) { cd[cnt] = dist; ck[cnt] = code; cnt++; }
        else ovf = true;
    }
    runm = fminf(runm, dist);
}

__global__ __launch_bounds__(NTHREADS)
void vq_main(const float* __restrict__ X, float* __restrict__ out, int rows, int K)
{
    extern __shared__ char smem[];
    uint32_t sb = smem_to_u32(smem);
    float* Xs  = (float*)(smem + SM_XS);
    float* Ee  = (float*)(smem + SM_EE);
    float* Xxs = (float*)(smem + SM_XX);
    float* red = (float*)(smem + SM_RED);
    int*  bIdx = (int*)(smem + SM_BIDX);

    int tid = threadIdx.x;
    int lane = tid & 31;
    int wid = tid >> 5;
    int r0blk = blockIdx.x * TM;

    // ---- Load X tile (coalesced float4) ----
    {
        const float4* Xg4 = (const float4*)X;
        float4* Xs4 = (float4*)Xs;
        int maxq = rows * (DD / 4) - 1;
#pragma unroll
        for (int i = 0; i < (TM * DD / 4) / NTHREADS; i++) {
            int idx = tid + i * NTHREADS;
            int g = r0blk * (DD / 4) + idx;
            Xs4[idx] = Xg4[g <= maxq ? g : maxq];
        }
    }
    __syncthreads();

    // ---- ||x||^2 per row (sequential, no fma: ref order) ----
    if (tid < TM) {
        float s = 0.f;
        const float* xr = Xs + tid * DD;
#pragma unroll
        for (int d = 0; d < DD; d++) s = __fadd_rn(s, __fmul_rn(xr[d], xr[d]));
        Xxs[tid] = s;
    }

    // ---- A hi/lo bf16 to swizzled smem (thread t: row t/2, half t%2) ----
    {
        int row = tid >> 1;
        int half = tid & 1;
        const float* xr = Xs + row * DD + half * 32;
#pragma unroll
        for (int i = 0; i < 16; i++) {
            float v0 = xr[2 * i], v1 = xr[2 * i + 1];
            __nv_bfloat16 h0 = __float2bfloat16(v0), h1 = __float2bfloat16(v1);
            __nv_bfloat16 l0 = __float2bfloat16(v0 - __bfloat162float(h0));
            __nv_bfloat16 l1 = __float2bfloat16(v1 - __bfloat162float(h1));
            __nv_bfloat162 hp; hp.x = h0; hp.y = h1;
            __nv_bfloat162 lp; lp.x = l0; lp.y = l1;
            uint32_t off = (uint32_t)row * 128 + (uint32_t)(half * 64 + i * 4);
            uint32_t sw = swz128(off);
            *(uint32_t*)(smem + SM_AHI + sw) = *(uint32_t*)&hp;
            *(uint32_t*)(smem + SM_ALO + sw) = *(uint32_t*)&lp;
        }
    }
    __syncthreads();

    // ---- A fragments (loop-invariant): warp strip rows [wid*16, wid*16+16) ----
    int wstrip = wid * 16;
    uint32_t ahi[4][4], alo[4][4];
    {
        int m = wstrip + (lane & 15);
        uint32_t kbh = (uint32_t)(lane >> 4) * 16;
#pragma unroll
        for (int ks = 0; ks < 4; ks++) {
            uint32_t off = (uint32_t)m * 128 + (uint32_t)ks * 32 + kbh;
            uint32_t sw = swz128(off);
            ldsm4(ahi[ks][0], ahi[ks][1], ahi[ks][2], ahi[ks][3], sb + SM_AHI + sw);
            ldsm4(alo[ks][0], alo[ks][1], alo[ks][2], alo[ks][3], sb + SM_ALO + sw);
        }
    }

    int rlo = wstrip + (lane >> 2);
    int rhi = rlo + 8;
    float xx0 = Xxs[rlo];
    float xx1 = Xxs[rhi];

    // candidate state: 2 rows per thread
    float candD[2][CAP];
    int   candK[2][CAP];
    int   cnt[2] = {0, 0};
    bool  ovf[2] = {false, false};
    float runm[2] = {3.4e38f, 3.4e38f};

    // B ldmatrix per-lane addressing: non-trans, rows = codes (n), k contiguous.
    // lanes 0-7: n 0-7, k-bytes 0   -> mat0 (b reg 0 of n-block 0)
    // lanes 8-15: n 0-7, k-bytes 16 -> mat1 (b reg 1 of n-block 0)
    // lanes 16-23: n 8-15, k-bytes 0  -> mat2 (b reg 0 of n-block 1)
    // lanes 24-31: n 8-15, k-bytes 16 -> mat3 (b reg 1 of n-block 1)
    uint32_t bcode = (uint32_t)((lane & 7) + ((lane & 16) ? 8 : 0));
    uint32_t bkb   = (uint32_t)(((lane >> 3) & 1) * 16);

    for (int t = 0; t < NKT; t++) {
        int kt = t * NTILE;
        __syncthreads();   // previous B/Ee fully consumed
        // ---- stage B hi/lo tile (64 codes x 64 d) with SW128 swizzle ----
        {
            const float4* shi = (const float4*)(g_Bhi + kt * DD);
            const float4* slo = (const float4*)(g_Blo + kt * DD);
#pragma unroll
            for (int i = 0; i < 2; i++) {
                int idx = tid + i * NTHREADS;       // 512 16B chunks
                uint32_t sw = swz128((uint32_t)idx * 16);
                *(float4*)(smem + SM_BHI + sw) = shi[idx];
                *(float4*)(smem + SM_BLO + sw) = slo[idx];
            }
            if (tid < NTILE) Ee[tid] = g_enorm[kt + tid];
        }
        __syncthreads();

        // ---- GEMM: 3-pass hi/lo, 8 n-tiles x 4 k-steps ----
        float acc[8][4];
#pragma unroll
        for (int i = 0; i < 8; i++) {
#pragma unroll
            for (int j = 0; j < 4; j++) acc[i][j] = 0.f;
        }
#pragma unroll
        for (int np = 0; np < 4; np++) {
            uint32_t n0 = (uint32_t)np * 16;
#pragma unroll
            for (int ks = 0; ks < 4; ks++) {
                uint32_t off = (n0 + bcode) * 128 + (uint32_t)ks * 32 + bkb;
                uint32_t sw = swz128(off);
                uint32_t bh0, bh1, bh2, bh3, bl0, bl1, bl2, bl3;
                ldsm4(bh0, bh1, bh2, bh3, sb + SM_BHI + sw);   // non-trans (fixed)
                ldsm4(bl0, bl1, bl2, bl3, sb + SM_BLO + sw);
                mma_bf16(acc[2 * np],     ahi[ks], bh0, bh1);
                mma_bf16(acc[2 * np],     ahi[ks], bl0, bl1);
                mma_bf16(acc[2 * np],     alo[ks], bh0, bh1);
                mma_bf16(acc[2 * np + 1], ahi[ks], bh2, bh3);
                mma_bf16(acc[2 * np + 1], ahi[ks], bl2, bl3);
                mma_bf16(acc[2 * np + 1], alo[ks], bh2, bh3);
            }
        }

        // ---- epilogue: candidates (C frag: rows rlo/rhi, cols 2*(lane&3)) ----
        int cb = 2 * (lane & 3);
#pragma unroll
        for (int nt = 0; nt < 8; nt++) {
            int cl = nt * 8 + cb;
            float e0 = Ee[cl], e1 = Ee[cl + 1];
            int c0 = kt + cl;
            float d00 = fmaf(-2.0f, acc[nt][0], xx0) + e0;
            float d01 = fmaf(-2.0f, acc[nt][1], xx0) + e1;
            float d10 = fmaf(-2.0f, acc[nt][2], xx1) + e0;
            float d11 = fmaf(-2.0f, acc[nt][3], xx1) + e1;
            cand_add(d00, c0,     candD[0], candK[0], cnt[0], ovf[0], runm[0]);
            cand_add(d01, c0 + 1, candD[0], candK[0], cnt[0], ovf[0], runm[0]);
            cand_add(d10, c0,     candD[1], candK[1], cnt[1], ovf[1], runm[1]);
            cand_add(d11, c0 + 1, candD[1], candK[1], cnt[1], ovf[1], runm[1]);
        }
    }

    // ---- exact rescore (reference chain) + quad reduce ----
#pragma unroll
    for (int s = 0; s < 2; s++) {
        int rr = (s == 0) ? rlo : rhi;
        float xxv = (s == 0) ? xx0 : xx1;
        const float* xr = Xs + rr * DD;
        float bd = 3.4e38f;
        int bk = 0x7fffffff;
        if (!ovf[s]) {
            for (int i = 0; i < cnt[s]; i++) {
                float d = exact_dist(xr, candK[s][i], xxv);
                if (d < bd) { bd = d; bk = candK[s][i]; }
            }
        } else {
            // exact scan of this lane's code subset (ascending k)
            int cb = 2 * (lane & 3);
            for (int tt = 0; tt < NKT; tt++) {
                for (int nt = 0; nt < 8; nt++) {
                    int c0 = tt * NTILE + nt * 8 + cb;
                    float d = exact_dist(xr, c0, xxv);
                    if (d < bd) { bd = d; bk = c0; }
                    d = exact_dist(xr, c0 + 1, xxv);
                    if (d < bd) { bd = d; bk = c0 + 1; }
                }
            }
        }
        // reduce across the 4 lanes of the quad (min dist, tie -> smaller idx)
#pragma unroll
        for (int m = 1; m < 4; m <<= 1) {
            float od = __shfl_xor_sync(0xffffffffu, bd, m);
            int   ok = __shfl_xor_sync(0xffffffffu, bk, m);
            if (od < bd || (od == bd && ok < bk)) { bd = od; bk = ok; }
        }
        if ((lane & 3) == 0) bIdx[rr] = bk;
    }
    __syncthreads();

    // ---- histogram (int atomics, deterministic) ----
    if (tid < TM && (r0blk + tid) < rows) atomicAdd(&g_hist[bIdx[tid]], 1);

    // ---- gather codebook rows, STE rounding, q write, SSE partial ----
    float sse = 0.f;
#pragma unroll
    for (int i = 0; i < (TM * DD) / NTHREADS; i++) {
        int e = tid + i * NTHREADS;
        int row = e >> 6;
        int d = e & 63;
        if (r0blk + row < rows) {
            float qv = g_ET[bIdx[row] * DD + d];
            float xv = Xs[row * DD + d];
            float df = __fsub_rn(qv, xv);
            out[(size_t)(r0blk + row) * DD + d] = __fadd_rn(xv, df);
            sse += df * df;
        }
    }
    red[tid] = sse;
    __syncthreads();
    for (int off = NTHREADS / 2; off > 0; off >>= 1) {
        if (tid < off) red[tid] += red[tid + off];
        __syncthreads();
    }
    if (tid == 0) g_partial[blockIdx.x] = red[0];
}

__global__ void vq_finalize(float* __restrict__ out, int nblocks, int rows, int K, long long outsz) {
    __shared__ float sh[1024];
    int tid = threadIdx.x;

    float s = 0.f;
    for (int i = tid; i < nblocks; i += blockDim.x) s += g_partial[i];
    sh[tid] = s;
    __syncthreads();
    for (int off = 512; off > 0; off >>= 1) {
        if (tid < off) sh[tid] += sh[tid + off];
        __syncthreads();
    }
    float sse = sh[0];
    __syncthreads();

    float invN = 1.0f / (float)rows;
    float ent = 0.f;
    for (int k = tid; k < K; k += blockDim.x) {
        float p = (float)g_hist[k] * invN;
        ent += p * logf(p + 1e-10f);
    }
    sh[tid] = ent;
    __syncthreads();
    for (int off = 512; off > 0; off >>= 1) {
        if (tid < off) sh[tid] += sh[tid + off];
        __syncthreads();
    }

    if (tid == 0) {
        long long nd = (long long)rows * DD;
        if (outsz > nd)     out[nd]     = 2.f * sse / (float)nd;
        if (outsz > nd + 1) out[nd + 1] = expf(-sh[0]);
    }
}

extern "C" void kernel_launch(void* const* d_in, const int* in_sizes, int n_in,
                              void* d_out, int out_size) {
    const float* X = (const float*)d_in[0];
    const float* E = (const float*)d_in[1];
    float* out = (float*)d_out;

    int nd = in_sizes[0];
    int rows = nd / DD;              // 131072
    int K = in_sizes[1] / DD;        // 1024

    int grid = (rows + TM - 1) / TM; // 1024

    cudaFuncSetAttribute(vq_main, cudaFuncAttributeMaxDynamicSharedMemorySize, SM_TOTAL);

    vq_setup<<<(K + 255) / 256, 256>>>(E, K);
    vq_main<<<grid, NTHREADS, SM_TOTAL>>>(X, out, rows, K);
    vq_finalize<<<1, 1024>>>(out, grid, rows, K, (long long)out_size);
}

// round 9
// speedup vs baseline: 1.7659x; 1.7204x over previous
#include <cuda_runtime.h>
#include <cuda_bf16.h>
#include <cstdint>
#include <math.h>

#define DD 64
#define KTOT 1024
#define TM 128
#define NTHREADS 256
#define NTILE 64
#define NKT (KTOT / NTILE)
#define THRESH 6e-3f

// ---------------- scratch (no allocations allowed) ----------------
__device__ float          g_enorm[KTOT];
__device__ float          g_ET[KTOT * DD];      // codebook rows, k-major, f32
__device__ __nv_bfloat16  g_Bhi[KTOT * DD];     // bf16 hi split, [code][d]
__device__ __nv_bfloat16  g_Blo[KTOT * DD];     // bf16 lo split, [code][d]
__device__ int            g_hist[KTOT];
__device__ float          g_partial[2048];

// ---------------- PTX helpers (baseline PTX only) ----------------
static __device__ __forceinline__ uint32_t smem_to_u32(const void* p) {
    uint32_t a;
    asm("{ .reg .u64 t; cvta.to.shared.u64 t, %1; cvt.u32.u64 %0, t; }" : "=r"(a) : "l"(p));
    return a;
}
static __device__ __forceinline__ void ldsm4(uint32_t& r0, uint32_t& r1,
    uint32_t& r2, uint32_t& r3, uint32_t addr) {
    asm volatile("ldmatrix.sync.aligned.m8n8.x4.shared.b16 {%0,%1,%2,%3}, [%4];"
        : "=r"(r0), "=r"(r1), "=r"(r2), "=r"(r3) : "r"(addr));
}
static __device__ __forceinline__ void mma_bf16(float* c, const uint32_t* a,
    uint32_t b0, uint32_t b1) {
    asm volatile(
        "mma.sync.aligned.m16n8k16.row.col.f32.bf16.bf16.f32 "
        "{%0,%1,%2,%3}, {%4,%5,%6,%7}, {%8,%9}, {%0,%1,%2,%3};"
        : "+f"(c[0]), "+f"(c[1]), "+f"(c[2]), "+f"(c[3])
        : "r"(a[0]), "r"(a[1]), "r"(a[2]), "r"(a[3]), "r"(b0), "r"(b1));
}
static __device__ __forceinline__ uint32_t swz128(uint32_t off) {
    return off ^ ((off >> 3) & 0x70u);
}

// ---------------- SMEM layout (bytes) ----------------
#define SM_XS    0          // 128*64 f32 = 32768
#define SM_AHI   32768      // 16384 (SW128 swizzled)
#define SM_ALO   49152      // 16384
#define SM_BHI   65536      // 8192
#define SM_BLO   73728      // 8192
#define SM_EE    81920      // 64 f32 = 256
#define SM_XX    82176      // 128 f32 = 512
#define SM_RED   82688      // 256 f32 = 1024
#define SM_BIDX  83712      // 128 int = 512
#define SM_UC    84224      // 1 int
#define SM_UL    84240      // 128 int = 512
#define SM_TOTAL 84800

// ---------------- setup: coalesced, 16 blocks x 256 thr ----------------
__global__ void vq_setup(const float* __restrict__ E, int K) {
    __shared__ float Et[64][65];
    int k0 = blockIdx.x * 64;
    int t = threadIdx.x;
    int kl = t & 63;
    int dq = t >> 6;
#pragma unroll
    for (int i = 0; i < 16; i++) {
        int d = dq + i * 4;
        Et[kl][d] = E[d * K + k0 + kl];     // coalesced: consecutive kl
    }
    __syncthreads();
    if (t < 64) {
        float s = 0.f;
#pragma unroll
        for (int d = 0; d < DD; d++) {
            float v = Et[t][d];
            s = __fadd_rn(s, __fmul_rn(v, v));   // sequential, no fma (ref order)
        }
        g_enorm[k0 + t] = s;
        g_hist[k0 + t] = 0;
    }
#pragma unroll
    for (int i = 0; i < 16; i++) {
        int k = k0 + dq + i * 4;
        float v = Et[dq + i * 4][kl];
        g_ET[k * DD + kl] = v;               // coalesced per code row
        __nv_bfloat16 h = __float2bfloat16(v);
        g_Bhi[k * DD + kl] = h;
        g_Blo[k * DD + kl] = __float2bfloat16(v - __bfloat162float(h));
    }
}

// exact reference-rounding distance (same chain that passed R2)
static __device__ __forceinline__ float exact_dist(const float* __restrict__ xr,
                                                   int k, float xxv) {
    float s = 0.f;
    const float4* ep = (const float4*)(g_ET + k * DD);
#pragma unroll
    for (int d4 = 0; d4 < DD / 4; d4++) {
        float4 e = ep[d4];
        float4 x = ((const float4*)xr)[d4];
        s = __fmaf_rn(x.x, e.x, s);
        s = __fmaf_rn(x.y, e.y, s);
        s = __fmaf_rn(x.z, e.z, s);
        s = __fmaf_rn(x.w, e.w, s);
    }
    return __fadd_rn(__fsub_rn(xxv, __fmul_rn(2.0f, s)), g_enorm[k]);
}

// branchless top-2 tracker
static __device__ __forceinline__ void upd2(float d, int c,
                                            float& m1, int& i1, float& m2) {
    bool lt = d < m1;
    m2 = fminf(m2, lt ? m1 : d);
    i1 = lt ? c : i1;
    m1 = lt ? d : m1;
}

__global__ __launch_bounds__(NTHREADS)
void vq_main(const float* __restrict__ X, float* __restrict__ out,
             int rows, int row0, int poff)
{
    extern __shared__ char smem[];
    uint32_t sb = smem_to_u32(smem);
    float* Xs  = (float*)(smem + SM_XS);
    float* Ee  = (float*)(smem + SM_EE);
    float* Xxs = (float*)(smem + SM_XX);
    float* red = (float*)(smem + SM_RED);
    int*  bIdx = (int*)(smem + SM_BIDX);
    int*  ucP  = (int*)(smem + SM_UC);
    int*  ulist= (int*)(smem + SM_UL);

    int tid = threadIdx.x;
    int lane = tid & 31;
    int wid = tid >> 5;
    int r0blk = row0 + blockIdx.x * TM;

    if (tid == 0) *ucP = 0;

    // ---- Load X tile (coalesced float4) ----
    {
        const float4* Xg4 = (const float4*)X;
        float4* Xs4 = (float4*)Xs;
        int maxq = rows * (DD / 4) - 1;
#pragma unroll
        for (int i = 0; i < (TM * DD / 4) / NTHREADS; i++) {
            int idx = tid + i * NTHREADS;
            int g = r0blk * (DD / 4) + idx;
            Xs4[idx] = Xg4[g <= maxq ? g : maxq];
        }
    }
    __syncthreads();

    // ---- ||x||^2 per row (sequential, no fma: ref order) ----
    if (tid < TM) {
        float s = 0.f;
        const float* xr = Xs + tid * DD;
#pragma unroll
        for (int d = 0; d < DD; d++) s = __fadd_rn(s, __fmul_rn(xr[d], xr[d]));
        Xxs[tid] = s;
    }

    // ---- A hi/lo bf16 to swizzled smem ----
    {
        int row = tid >> 1;
        int half = tid & 1;
        const float* xr = Xs + row * DD + half * 32;
#pragma unroll
        for (int i = 0; i < 16; i++) {
            float v0 = xr[2 * i], v1 = xr[2 * i + 1];
            __nv_bfloat16 h0 = __float2bfloat16(v0), h1 = __float2bfloat16(v1);
            __nv_bfloat16 l0 = __float2bfloat16(v0 - __bfloat162float(h0));
            __nv_bfloat16 l1 = __float2bfloat16(v1 - __bfloat162float(h1));
            __nv_bfloat162 hp; hp.x = h0; hp.y = h1;
            __nv_bfloat162 lp; lp.x = l0; lp.y = l1;
            uint32_t off = (uint32_t)row * 128 + (uint32_t)(half * 64 + i * 4);
            uint32_t sw = swz128(off);
            *(uint32_t*)(smem + SM_AHI + sw) = *(uint32_t*)&hp;
            *(uint32_t*)(smem + SM_ALO + sw) = *(uint32_t*)&lp;
        }
    }
    __syncthreads();

    // ---- A fragments (loop-invariant): warp strip rows [wid*16, +16) ----
    int wstrip = wid * 16;
    uint32_t ahi[4][4], alo[4][4];
    {
        int m = wstrip + (lane & 15);
        uint32_t kbh = (uint32_t)(lane >> 4) * 16;
#pragma unroll
        for (int ks = 0; ks < 4; ks++) {
            uint32_t off = (uint32_t)m * 128 + (uint32_t)ks * 32 + kbh;
            uint32_t sw = swz128(off);
            ldsm4(ahi[ks][0], ahi[ks][1], ahi[ks][2], ahi[ks][3], sb + SM_AHI + sw);
            ldsm4(alo[ks][0], alo[ks][1], alo[ks][2], alo[ks][3], sb + SM_ALO + sw);
        }
    }

    int rlo = wstrip + (lane >> 2);
    int rhi = rlo + 8;
    float xx0 = Xxs[rlo];
    float xx1 = Xxs[rhi];

    // top-2 state per row
    float m1a = 3.4e38f, m2a = 3.4e38f;
    float m1b = 3.4e38f, m2b = 3.4e38f;
    int i1a = 0, i1b = 0;

    uint32_t bcode = (uint32_t)((lane & 7) + ((lane & 16) ? 8 : 0));
    uint32_t bkb   = (uint32_t)(((lane >> 3) & 1) * 16);

    // ---- prefetch tile 0 ----
    float4 ph0, ph1, pl0, pl1;
    float pe = 0.f;
    {
        const float4* shi = (const float4*)(g_Bhi);
        const float4* slo = (const float4*)(g_Blo);
        ph0 = shi[tid]; ph1 = shi[tid + NTHREADS];
        pl0 = slo[tid]; pl1 = slo[tid + NTHREADS];
        if (tid < NTILE) pe = g_enorm[tid];
    }
    {
        uint32_t sw0 = swz128((uint32_t)tid * 16);
        uint32_t sw1 = swz128((uint32_t)(tid + NTHREADS) * 16);
        *(float4*)(smem + SM_BHI + sw0) = ph0;
        *(float4*)(smem + SM_BHI + sw1) = ph1;
        *(float4*)(smem + SM_BLO + sw0) = pl0;
        *(float4*)(smem + SM_BLO + sw1) = pl1;
        if (tid < NTILE) Ee[tid] = pe;
    }
    __syncthreads();

    for (int t = 0; t < NKT; t++) {
        int kt = t * NTILE;
        // prefetch next tile into regs (overlaps MMA below)
        if (t + 1 < NKT) {
            const float4* shi = (const float4*)(g_Bhi + (kt + NTILE) * DD);
            const float4* slo = (const float4*)(g_Blo + (kt + NTILE) * DD);
            ph0 = shi[tid]; ph1 = shi[tid + NTHREADS];
            pl0 = slo[tid]; pl1 = slo[tid + NTHREADS];
            if (tid < NTILE) pe = g_enorm[kt + NTILE + tid];
        }

        // ---- GEMM: 3-pass hi/lo, 4 n-pairs x 4 k-steps ----
        float acc[8][4];
#pragma unroll
        for (int i = 0; i < 8; i++) {
#pragma unroll
            for (int j = 0; j < 4; j++) acc[i][j] = 0.f;
        }
#pragma unroll
        for (int np = 0; np < 4; np++) {
            uint32_t n0 = (uint32_t)np * 16;
#pragma unroll
            for (int ks = 0; ks < 4; ks++) {
                uint32_t off = (n0 + bcode) * 128 + (uint32_t)ks * 32 + bkb;
                uint32_t sw = swz128(off);
                uint32_t bh0, bh1, bh2, bh3, bl0, bl1, bl2, bl3;
                ldsm4(bh0, bh1, bh2, bh3, sb + SM_BHI + sw);
                ldsm4(bl0, bl1, bl2, bl3, sb + SM_BLO + sw);
                mma_bf16(acc[2 * np],     ahi[ks], bh0, bh1);
                mma_bf16(acc[2 * np],     ahi[ks], bl0, bl1);
                mma_bf16(acc[2 * np],     alo[ks], bh0, bh1);
                mma_bf16(acc[2 * np + 1], ahi[ks], bh2, bh3);
                mma_bf16(acc[2 * np + 1], ahi[ks], bl2, bl3);
                mma_bf16(acc[2 * np + 1], alo[ks], bh2, bh3);
            }
        }

        // ---- epilogue: branchless top-2 tracking ----
        int cb = 2 * (lane & 3);
#pragma unroll
        for (int nt = 0; nt < 8; nt++) {
            int cl = nt * 8 + cb;
            float e0 = Ee[cl], e1 = Ee[cl + 1];
            int c0 = kt + cl;
            float d00 = fmaf(-2.0f, acc[nt][0], xx0) + e0;
            float d01 = fmaf(-2.0f, acc[nt][1], xx0) + e1;
            float d10 = fmaf(-2.0f, acc[nt][2], xx1) + e0;
            float d11 = fmaf(-2.0f, acc[nt][3], xx1) + e1;
            upd2(d00, c0,     m1a, i1a, m2a);
            upd2(d01, c0 + 1, m1a, i1a, m2a);
            upd2(d10, c0,     m1b, i1b, m2b);
            upd2(d11, c0 + 1, m1b, i1b, m2b);
        }

        __syncthreads();   // B + Ee consumed
        if (t + 1 < NKT) {
            uint32_t sw0 = swz128((uint32_t)tid * 16);
            uint32_t sw1 = swz128((uint32_t)(tid + NTHREADS) * 16);
            *(float4*)(smem + SM_BHI + sw0) = ph0;
            *(float4*)(smem + SM_BHI + sw1) = ph1;
            *(float4*)(smem + SM_BLO + sw0) = pl0;
            *(float4*)(smem + SM_BLO + sw1) = pl1;
            if (tid < NTILE) Ee[tid] = pe;
            __syncthreads();
        }
    }

    // ---- quad reduce (m1, i1, m2) and decide ----
#pragma unroll
    for (int s = 0; s < 2; s++) {
        float m1 = (s == 0) ? m1a : m1b;
        float m2 = (s == 0) ? m2a : m2b;
        int   i1 = (s == 0) ? i1a : i1b;
        int   rr = (s == 0) ? rlo : rhi;
#pragma unroll
        for (int m = 1; m < 4; m <<= 1) {
            float om1 = __shfl_xor_sync(0xffffffffu, m1, m);
            int   oi1 = __shfl_xor_sync(0xffffffffu, i1, m);
            float om2 = __shfl_xor_sync(0xffffffffu, m2, m);
            float hi = fmaxf(m1, om1);
            m2 = fminf(fminf(m2, om2), hi);
            if (om1 < m1 || (om1 == m1 && oi1 < i1)) { m1 = om1; i1 = oi1; }
        }
        if ((lane & 3) == 0) {
            bIdx[rr] = i1;
            if (m2 - m1 < THRESH) {         // ambiguous -> exact rescan
                int u = atomicAdd(ucP, 1);
                ulist[u] = rr;
            }
        }
    }
    __syncthreads();

    // ---- exact full scan for ambiguous rows (reference chain, warp per row) ----
    {
        int nu = *ucP;
        for (int u = wid; u < nu; u += 8) {
            int rr = ulist[u];
            const float* xr = Xs + rr * DD;
            float xxv = Xxs[rr];
            float bd = 3.4e38f;
            int bk = 0;
            int cbase = lane * 32;
            for (int c = cbase; c < cbase + 32; c++) {
                float d = exact_dist(xr, c, xxv);
                if (d < bd) { bd = d; bk = c; }   // ascending k: first-index ties
            }
#pragma unroll
            for (int m = 1; m < 32; m <<= 1) {
                float od = __shfl_xor_sync(0xffffffffu, bd, m);
                int   ok = __shfl_xor_sync(0xffffffffu, bk, m);
                if (od < bd || (od == bd && ok < bk)) { bd = od; bk = ok; }
            }
            if (lane == 0) bIdx[rr] = bk;
        }
    }
    __syncthreads();

    // ---- histogram (int atomics, deterministic) ----
    if (tid < TM && (r0blk + tid) < rows) atomicAdd(&g_hist[bIdx[tid]], 1);

    // ---- gather codebook rows, STE rounding, q write, SSE partial ----
    float sse = 0.f;
#pragma unroll
    for (int i = 0; i < (TM * DD) / NTHREADS; i++) {
        int e = tid + i * NTHREADS;
        int row = e >> 6;
        int d = e & 63;
        if (r0blk + row < rows) {
            float qv = g_ET[bIdx[row] * DD + d];
            float xv = Xs[row * DD + d];
            float df = __fsub_rn(qv, xv);
            out[(size_t)(r0blk + row) * DD + d] = __fadd_rn(xv, df);
            sse += df * df;
        }
    }
    red[tid] = sse;
    __syncthreads();
    for (int off = NTHREADS / 2; off > 0; off >>= 1) {
        if (tid < off) red[tid] += red[tid + off];
        __syncthreads();
    }
    if (tid == 0) g_partial[poff + blockIdx.x] = red[0];
}

__global__ void vq_finalize(float* __restrict__ out, int nblocks, int rows, int K, long long outsz) {
    __shared__ float sh[1024];
    int tid = threadIdx.x;

    float s = 0.f;
    for (int i = tid; i < nblocks; i += blockDim.x) s += g_partial[i];
    sh[tid] = s;
    __syncthreads();
    for (int off = 512; off > 0; off >>= 1) {
        if (tid < off) sh[tid] += sh[tid + off];
        __syncthreads();
    }
    float sse = sh[0];
    __syncthreads();

    float invN = 1.0f / (float)rows;
    float ent = 0.f;
    for (int k = tid; k < K; k += blockDim.x) {
        float p = (float)g_hist[k] * invN;
        ent += p * logf(p + 1e-10f);
    }
    sh[tid] = ent;
    __syncthreads();
    for (int off = 512; off > 0; off >>= 1) {
        if (tid < off) sh[tid] += sh[tid + off];
        __syncthreads();
    }

    if (tid == 0) {
        long long nd = (long long)rows * DD;
        if (outsz > nd)     out[nd]     = 2.f * sse / (float)nd;
        if (outsz > nd + 1) out[nd + 1] = expf(-sh[0]);
    }
}

extern "C" void kernel_launch(void* const* d_in, const int* in_sizes, int n_in,
                              void* d_out, int out_size) {
    const float* X = (const float*)d_in[0];
    const float* E = (const float*)d_in[1];
    float* out = (float*)d_out;

    int nd = in_sizes[0];
    int rows = nd / DD;              // 131072
    int K = in_sizes[1] / DD;        // 1024

    int grid = (rows + TM - 1) / TM; // 1024
    int half = grid / 2;             // 512

    cudaFuncSetAttribute(vq_main, cudaFuncAttributeMaxDynamicSharedMemorySize, SM_TOTAL);

    vq_setup<<<K / 64, 256>>>(E, K);
    vq_main<<<half, NTHREADS, SM_TOTAL>>>(X, out, rows, 0, 0);
    vq_main<<<grid - half, NTHREADS, SM_TOTAL>>>(X, out, rows, half * TM, half);
    vq_finalize<<<1, 1024>>>(out, grid, rows, K, (long long)out_size);
}